// round 11
// baseline (speedup 1.0000x reference)
#include <cuda_runtime.h>
#include <cuda_fp16.h>
#include <stdint.h>

// Problem constants (fixed by the reference)
#define N_NODES   100000
#define IN_CH     2048
#define OUT_CH    128
#define NNZ_FEAT  2000000
#define NNZ_ADJ   1600000
#define NNZ_TOT   (NNZ_FEAT + NNZ_ADJ)

#define SCAN_BLOCK 1024
#define SCAN_NBLK  ((N_NODES + SCAN_BLOCK - 1) / SCAN_BLOCK)   // 98

// ---------------- device scratch (no runtime allocation allowed) ------------
__device__ __half g_h0[(size_t)N_NODES * OUT_CH];   // 25.6 MB fp16 intermediates
__device__ __half g_h1[(size_t)N_NODES * OUT_CH];   // 25.6 MB
__device__ __half g_Wh[(size_t)IN_CH * OUT_CH];     // 0.5 MB fp16 copy of W

__device__ int2 g_feat_pack[NNZ_FEAT];              // (col, fp32-val-bits) row-sorted
__device__ int2 g_adj_pack[NNZ_ADJ];

__device__ int g_rowptr_feat[N_NODES + 1];
__device__ int g_rowptr_adj[N_NODES + 1];
// Fused scratch: segment 0 = feat, segment 1 = adj (offset N_NODES)
__device__ int g_cnt[2 * N_NODES];
__device__ int g_incl[2 * N_NODES];
__device__ int g_cursor[2 * N_NODES];
__device__ int g_bsum[2 * SCAN_NBLK];

// ---------------- fused CSR build: one pass for BOTH matrices ---------------
__global__ void __launch_bounds__(256)
hist2_kernel(const int* __restrict__ feat_rows, const int* __restrict__ adj_rows,
             int* __restrict__ cnt)
{
    int i = blockIdx.x * blockDim.x + threadIdx.x;
    if (i < NNZ_FEAT)      atomicAdd(cnt + feat_rows[i], 1);
    else if (i < NNZ_TOT)  atomicAdd(cnt + N_NODES + adj_rows[i - NNZ_FEAT], 1);
}

// Blocks [0,98) scan the feat segment, [98,196) the adj segment.
__global__ void __launch_bounds__(SCAN_BLOCK)
scan_block2_kernel(const int* __restrict__ cnt, int* __restrict__ incl,
                   int* __restrict__ bsum)
{
    __shared__ int s[SCAN_BLOCK];
    int seg  = (blockIdx.x >= SCAN_NBLK) ? 1 : 0;
    int blk  = blockIdx.x - seg * SCAN_NBLK;
    int idx  = blk * SCAN_BLOCK + threadIdx.x;          // index within segment
    int off  = seg * N_NODES;
    int x = (idx < N_NODES) ? cnt[off + idx] : 0;
    s[threadIdx.x] = x;
    __syncthreads();
    #pragma unroll
    for (int o = 1; o < SCAN_BLOCK; o <<= 1) {
        int t = (threadIdx.x >= o) ? s[threadIdx.x - o] : 0;
        __syncthreads();
        s[threadIdx.x] += t;
        __syncthreads();
    }
    if (idx < N_NODES) incl[off + idx] = s[threadIdx.x];
    if (threadIdx.x == SCAN_BLOCK - 1) bsum[blockIdx.x] = s[SCAN_BLOCK - 1];
}

// Exclusive-scan both 98-entry bsum segments: one warp per segment, shfl scan.
__global__ void __launch_bounds__(64)
scan_bsum2_kernel(int* __restrict__ bsum)
{
    int warp = threadIdx.x >> 5;      // segment
    int lane = threadIdx.x & 31;
    int base = warp * SCAN_NBLK;
    int carry = 0;
    #pragma unroll
    for (int c = 0; c < SCAN_NBLK; c += 32) {
        int idx = c + lane;
        int x = (idx < SCAN_NBLK) ? bsum[base + idx] : 0;
        int v = x;
        #pragma unroll
        for (int o = 1; o < 32; o <<= 1) {
            int t = __shfl_up_sync(0xffffffffu, v, o);
            if (lane >= o) v += t;
        }
        if (idx < SCAN_NBLK) bsum[base + idx] = v - x + carry;   // exclusive
        carry += __shfl_sync(0xffffffffu, v, 31);                // chunk total
    }
}

__global__ void __launch_bounds__(256)
finalize2_kernel(const int* __restrict__ cnt, const int* __restrict__ incl,
                 const int* __restrict__ bsum,
                 int* __restrict__ rp_f, int* __restrict__ rp_a,
                 int* __restrict__ cursor)
{
    int i = blockIdx.x * blockDim.x + threadIdx.x;
    if (i >= 2 * N_NODES) return;
    int seg   = (i >= N_NODES) ? 1 : 0;
    int local = i - seg * N_NODES;
    int ex = incl[i] - cnt[i] + bsum[seg * SCAN_NBLK + local / SCAN_BLOCK];
    int* rp = seg ? rp_a : rp_f;
    rp[local]  = ex;
    cursor[i]  = ex;
    if (local == 0) rp[N_NODES] = seg ? NNZ_ADJ : NNZ_FEAT;
}

__global__ void __launch_bounds__(256)
scatter2_kernel(const int* __restrict__ feat_rows, const int* __restrict__ feat_cols,
                const float* __restrict__ feat_vals,
                const int* __restrict__ adj_rows, const int* __restrict__ adj_cols,
                const float* __restrict__ adj_vals,
                int* __restrict__ cursor,
                int2* __restrict__ pk_f, int2* __restrict__ pk_a)
{
    int i = blockIdx.x * blockDim.x + threadIdx.x;
    if (i < NNZ_FEAT) {
        int r = feat_rows[i];
        int p = atomicAdd(cursor + r, 1);
        pk_f[p] = make_int2(feat_cols[i], __float_as_int(feat_vals[i]));
    } else if (i < NNZ_TOT) {
        int j = i - NNZ_FEAT;
        int r = adj_rows[j];
        int p = atomicAdd(cursor + N_NODES + r, 1);
        pk_a[p] = make_int2(adj_cols[j], __float_as_int(adj_vals[j]));
    }
}

// ---------------- W fp32 -> fp16 conversion ---------------------------------
__global__ void __launch_bounds__(256)
convert_w_kernel(const float* __restrict__ w, __half* __restrict__ wh, int n)
{
    int i = blockIdx.x * blockDim.x + threadIdx.x;
    if (i < n) wh[i] = __float2half_rn(w[i]);
}

// ---------------- gather SpMM (fp16 dense operand) --------------------------
// out[r,:] = sum_j val_j * dense[col_j,:]   dense rows = 128 halves = 256B.
// One warp per output row; lane l owns channels [4l, 4l+4) (one uint2).
// fp32 accumulation. Inner loop unrolled x8 for MLP.
__device__ __forceinline__ void fma_row(float4& acc, float v, uint2 d)
{
    __half2 lo = *reinterpret_cast<__half2*>(&d.x);
    __half2 hi = *reinterpret_cast<__half2*>(&d.y);
    float2 f0 = __half22float2(lo);
    float2 f1 = __half22float2(hi);
    acc.x += v * f0.x; acc.y += v * f0.y;
    acc.z += v * f1.x; acc.w += v * f1.y;
}

template<bool RELU_BIAS, bool OUT_HALF>
__global__ void __launch_bounds__(256)
spmm_gather_kernel(const int* __restrict__ rowptr, const int2* __restrict__ pack,
                   const __half* __restrict__ dense, const float* __restrict__ bias,
                   void* __restrict__ outv, int n_rows)
{
    int w    = (blockIdx.x * blockDim.x + threadIdx.x) >> 5;
    int lane = threadIdx.x & 31;
    if (w >= n_rows) return;

    int start = __ldg(rowptr + w);
    int end   = __ldg(rowptr + w + 1);

    float4 acc = make_float4(0.f, 0.f, 0.f, 0.f);

    for (int base = start; base < end; base += 32) {
        int n = end - base; if (n > 32) n = 32;
        int2 p = make_int2(0, 0);
        if (lane < n) p = __ldg(pack + base + lane);

        int k = 0;
        for (; k + 8 <= n; k += 8) {
            int c[8]; float v[8]; uint2 d[8];
            #pragma unroll
            for (int u = 0; u < 8; u++) {
                c[u] = __shfl_sync(0xffffffffu, p.x, k + u);
                v[u] = __int_as_float(__shfl_sync(0xffffffffu, p.y, k + u));
            }
            #pragma unroll
            for (int u = 0; u < 8; u++)
                d[u] = __ldg(reinterpret_cast<const uint2*>(dense + (size_t)c[u] * OUT_CH) + lane);
            #pragma unroll
            for (int u = 0; u < 8; u++)
                fma_row(acc, v[u], d[u]);
        }
        for (; k + 4 <= n; k += 4) {
            int c[4]; float v[4]; uint2 d[4];
            #pragma unroll
            for (int u = 0; u < 4; u++) {
                c[u] = __shfl_sync(0xffffffffu, p.x, k + u);
                v[u] = __int_as_float(__shfl_sync(0xffffffffu, p.y, k + u));
            }
            #pragma unroll
            for (int u = 0; u < 4; u++)
                d[u] = __ldg(reinterpret_cast<const uint2*>(dense + (size_t)c[u] * OUT_CH) + lane);
            #pragma unroll
            for (int u = 0; u < 4; u++)
                fma_row(acc, v[u], d[u]);
        }
        for (; k < n; k++) {
            int   c0 = __shfl_sync(0xffffffffu, p.x, k);
            float v0 = __int_as_float(__shfl_sync(0xffffffffu, p.y, k));
            uint2 d0 = __ldg(reinterpret_cast<const uint2*>(dense + (size_t)c0 * OUT_CH) + lane);
            fma_row(acc, v0, d0);
        }
    }

    if (RELU_BIAS) {
        float4 b = __ldg(reinterpret_cast<const float4*>(bias) + lane);
        acc.x = fmaxf(acc.x + b.x, 0.f);
        acc.y = fmaxf(acc.y + b.y, 0.f);
        acc.z = fmaxf(acc.z + b.z, 0.f);
        acc.w = fmaxf(acc.w + b.w, 0.f);
    }

    if (OUT_HALF) {
        __half2 lo = __floats2half2_rn(acc.x, acc.y);
        __half2 hi = __floats2half2_rn(acc.z, acc.w);
        uint2 st;
        st.x = *reinterpret_cast<uint32_t*>(&lo);
        st.y = *reinterpret_cast<uint32_t*>(&hi);
        reinterpret_cast<uint2*>(outv)[(size_t)w * 32 + lane] = st;
    } else {
        reinterpret_cast<float4*>(outv)[(size_t)w * 32 + lane] = acc;
    }
}

// ---------------- launch ----------------------------------------------------
extern "C" void kernel_launch(void* const* d_in, const int* in_sizes, int n_in,
                              void* d_out, int out_size)
{
    const int*   feat_rows = (const int*)  d_in[0];
    const int*   feat_cols = (const int*)  d_in[1];
    const float* feat_vals = (const float*)d_in[2];
    const int*   adj_rows  = (const int*)  d_in[3];
    const int*   adj_cols  = (const int*)  d_in[4];
    const float* adj_vals  = (const float*)d_in[5];
    const float* weight    = (const float*)d_in[6];
    const float* bias      = (const float*)d_in[7];
    float*       out       = (float*)      d_out;

    __half *h0, *h1, *wh;
    int *rp_f, *rp_a, *cnt, *incl, *bsum, *cursor;
    int2 *pk_f, *pk_a;
    cudaGetSymbolAddress((void**)&h0,     g_h0);
    cudaGetSymbolAddress((void**)&h1,     g_h1);
    cudaGetSymbolAddress((void**)&wh,     g_Wh);
    cudaGetSymbolAddress((void**)&rp_f,   g_rowptr_feat);
    cudaGetSymbolAddress((void**)&rp_a,   g_rowptr_adj);
    cudaGetSymbolAddress((void**)&cnt,    g_cnt);
    cudaGetSymbolAddress((void**)&incl,   g_incl);
    cudaGetSymbolAddress((void**)&bsum,   g_bsum);
    cudaGetSymbolAddress((void**)&cursor, g_cursor);
    cudaGetSymbolAddress((void**)&pk_f,   g_feat_pack);
    cudaGetSymbolAddress((void**)&pk_a,   g_adj_pack);

    // W -> fp16
    convert_w_kernel<<<(IN_CH * OUT_CH + 255) / 256, 256>>>(weight, wh, IN_CH * OUT_CH);

    // Fused CSR build for both matrices (6 launches total).
    cudaMemsetAsync(cnt, 0, 2 * N_NODES * sizeof(int));
    hist2_kernel<<<(NNZ_TOT + 255) / 256, 256>>>(feat_rows, adj_rows, cnt);
    scan_block2_kernel<<<2 * SCAN_NBLK, SCAN_BLOCK>>>(cnt, incl, bsum);
    scan_bsum2_kernel<<<1, 64>>>(bsum);
    finalize2_kernel<<<(2 * N_NODES + 255) / 256, 256>>>(cnt, incl, bsum,
                                                         rp_f, rp_a, cursor);
    scatter2_kernel<<<(NNZ_TOT + 255) / 256, 256>>>(feat_rows, feat_cols, feat_vals,
                                                    adj_rows, adj_cols, adj_vals,
                                                    cursor, pk_f, pk_a);

    const int gather_blocks = (N_NODES * 32 + 255) / 256;   // one warp per row

    // Layer 1: h0 = relu(feat @ W + bias), stored fp16
    spmm_gather_kernel<true,  true ><<<gather_blocks, 256>>>(rp_f, pk_f, wh, bias,
                                                             h0, N_NODES);
    // Iterations 2..3: fp16 -> fp16
    spmm_gather_kernel<false, true ><<<gather_blocks, 256>>>(rp_a, pk_a, h0, nullptr,
                                                             h1, N_NODES);
    spmm_gather_kernel<false, true ><<<gather_blocks, 256>>>(rp_a, pk_a, h1, nullptr,
                                                             h0, N_NODES);
    // Iteration 4: fp16 -> fp32 final output (no quantization on last write)
    spmm_gather_kernel<false, false><<<gather_blocks, 256>>>(rp_a, pk_a, h0, nullptr,
                                                             out, N_NODES);
}

// round 14
// speedup vs baseline: 1.0853x; 1.0853x over previous
#include <cuda_runtime.h>
#include <cuda_fp16.h>
#include <stdint.h>

// Problem constants (fixed by the reference)
#define N_NODES   100000
#define IN_CH     2048
#define OUT_CH    128
#define NNZ_FEAT  2000000
#define NNZ_ADJ   1600000
#define NNZ_TOT   (NNZ_FEAT + NNZ_ADJ)

#define SCAN_BLOCK 1024
#define SCAN_NBLK  ((N_NODES + SCAN_BLOCK - 1) / SCAN_BLOCK)   // 98

// ---------------- device scratch (no runtime allocation allowed) ------------
__device__ __half g_h0[(size_t)N_NODES * OUT_CH];   // 25.6 MB fp16 intermediates
__device__ __half g_h1[(size_t)N_NODES * OUT_CH];   // 25.6 MB
__device__ __half g_Wh[(size_t)IN_CH * OUT_CH];     // 0.5 MB fp16 copy of W

__device__ int2 g_feat_pack[NNZ_FEAT];              // (col, fp32-val-bits) row-sorted
__device__ int2 g_adj_pack[NNZ_ADJ];

__device__ int g_rowptr_feat[N_NODES + 1];
__device__ int g_rowptr_adj[N_NODES + 1];
// Fused scratch: segment 0 = feat, segment 1 = adj (offset N_NODES)
__device__ int g_cnt[2 * N_NODES];
__device__ int g_incl[2 * N_NODES];
__device__ int g_cursor[2 * N_NODES];
__device__ int g_bsum[2 * SCAN_NBLK];

// ---------------- fused CSR build: one pass for BOTH matrices ---------------
__global__ void __launch_bounds__(256)
hist2_kernel(const int* __restrict__ feat_rows, const int* __restrict__ adj_rows,
             int* __restrict__ cnt)
{
    int i = blockIdx.x * blockDim.x + threadIdx.x;
    if (i < NNZ_FEAT)      atomicAdd(cnt + feat_rows[i], 1);
    else if (i < NNZ_TOT)  atomicAdd(cnt + N_NODES + adj_rows[i - NNZ_FEAT], 1);
}

// Blocks [0,98) scan the feat segment, [98,196) the adj segment.
__global__ void __launch_bounds__(SCAN_BLOCK)
scan_block2_kernel(const int* __restrict__ cnt, int* __restrict__ incl,
                   int* __restrict__ bsum)
{
    __shared__ int s[SCAN_BLOCK];
    int seg  = (blockIdx.x >= SCAN_NBLK) ? 1 : 0;
    int blk  = blockIdx.x - seg * SCAN_NBLK;
    int idx  = blk * SCAN_BLOCK + threadIdx.x;          // index within segment
    int off  = seg * N_NODES;
    int x = (idx < N_NODES) ? cnt[off + idx] : 0;
    s[threadIdx.x] = x;
    __syncthreads();
    #pragma unroll
    for (int o = 1; o < SCAN_BLOCK; o <<= 1) {
        int t = (threadIdx.x >= o) ? s[threadIdx.x - o] : 0;
        __syncthreads();
        s[threadIdx.x] += t;
        __syncthreads();
    }
    if (idx < N_NODES) incl[off + idx] = s[threadIdx.x];
    if (threadIdx.x == SCAN_BLOCK - 1) bsum[blockIdx.x] = s[SCAN_BLOCK - 1];
}

// Exclusive-scan both 98-entry bsum segments: one warp per segment, shfl scan.
__global__ void __launch_bounds__(64)
scan_bsum2_kernel(int* __restrict__ bsum)
{
    int warp = threadIdx.x >> 5;      // segment
    int lane = threadIdx.x & 31;
    int base = warp * SCAN_NBLK;
    int carry = 0;
    #pragma unroll
    for (int c = 0; c < SCAN_NBLK; c += 32) {
        int idx = c + lane;
        int x = (idx < SCAN_NBLK) ? bsum[base + idx] : 0;
        int v = x;
        #pragma unroll
        for (int o = 1; o < 32; o <<= 1) {
            int t = __shfl_up_sync(0xffffffffu, v, o);
            if (lane >= o) v += t;
        }
        if (idx < SCAN_NBLK) bsum[base + idx] = v - x + carry;   // exclusive
        carry += __shfl_sync(0xffffffffu, v, 31);                // chunk total
    }
}

__global__ void __launch_bounds__(256)
finalize2_kernel(const int* __restrict__ cnt, const int* __restrict__ incl,
                 const int* __restrict__ bsum,
                 int* __restrict__ rp_f, int* __restrict__ rp_a,
                 int* __restrict__ cursor)
{
    int i = blockIdx.x * blockDim.x + threadIdx.x;
    if (i >= 2 * N_NODES) return;
    int seg   = (i >= N_NODES) ? 1 : 0;
    int local = i - seg * N_NODES;
    int ex = incl[i] - cnt[i] + bsum[seg * SCAN_NBLK + local / SCAN_BLOCK];
    int* rp = seg ? rp_a : rp_f;
    rp[local]  = ex;
    cursor[i]  = ex;
    if (local == 0) rp[N_NODES] = seg ? NNZ_ADJ : NNZ_FEAT;
}

__global__ void __launch_bounds__(256)
scatter2_kernel(const int* __restrict__ feat_rows, const int* __restrict__ feat_cols,
                const float* __restrict__ feat_vals,
                const int* __restrict__ adj_rows, const int* __restrict__ adj_cols,
                const float* __restrict__ adj_vals,
                int* __restrict__ cursor,
                int2* __restrict__ pk_f, int2* __restrict__ pk_a)
{
    int i = blockIdx.x * blockDim.x + threadIdx.x;
    if (i < NNZ_FEAT) {
        int r = feat_rows[i];
        int p = atomicAdd(cursor + r, 1);
        pk_f[p] = make_int2(feat_cols[i], __float_as_int(feat_vals[i]));
    } else if (i < NNZ_TOT) {
        int j = i - NNZ_FEAT;
        int r = adj_rows[j];
        int p = atomicAdd(cursor + N_NODES + r, 1);
        pk_a[p] = make_int2(adj_cols[j], __float_as_int(adj_vals[j]));
    }
}

// ---------------- W fp32 -> fp16 conversion ---------------------------------
__global__ void __launch_bounds__(256)
convert_w_kernel(const float* __restrict__ w, __half* __restrict__ wh, int n)
{
    int i = blockIdx.x * blockDim.x + threadIdx.x;
    if (i < n) wh[i] = __float2half_rn(w[i]);
}

// ---------------- gather SpMM (fp16 dense operand) --------------------------
// out[r,:] = sum_j val_j * dense[col_j,:]   dense rows = 128 halves = 256B.
// One warp per output row; lane l owns channels [4l, 4l+4) (one uint2).
// fp32 accumulation. Inner loop unrolled x4 (measured best: x8 drops occupancy
// from ~8 to ~4 blocks/SM via register pressure and cost ~22us — R10 post-mortem).
__device__ __forceinline__ void fma_row(float4& acc, float v, uint2 d)
{
    __half2 lo = *reinterpret_cast<__half2*>(&d.x);
    __half2 hi = *reinterpret_cast<__half2*>(&d.y);
    float2 f0 = __half22float2(lo);
    float2 f1 = __half22float2(hi);
    acc.x += v * f0.x; acc.y += v * f0.y;
    acc.z += v * f1.x; acc.w += v * f1.y;
}

template<bool RELU_BIAS, bool OUT_HALF>
__global__ void __launch_bounds__(256)
spmm_gather_kernel(const int* __restrict__ rowptr, const int2* __restrict__ pack,
                   const __half* __restrict__ dense, const float* __restrict__ bias,
                   void* __restrict__ outv, int n_rows)
{
    int w    = (blockIdx.x * blockDim.x + threadIdx.x) >> 5;
    int lane = threadIdx.x & 31;
    if (w >= n_rows) return;

    int start = __ldg(rowptr + w);
    int end   = __ldg(rowptr + w + 1);

    float4 acc = make_float4(0.f, 0.f, 0.f, 0.f);

    for (int base = start; base < end; base += 32) {
        int n = end - base; if (n > 32) n = 32;
        int2 p = make_int2(0, 0);
        if (lane < n) p = __ldg(pack + base + lane);

        int k = 0;
        for (; k + 4 <= n; k += 4) {
            int   c0 = __shfl_sync(0xffffffffu, p.x, k);
            int   c1 = __shfl_sync(0xffffffffu, p.x, k + 1);
            int   c2 = __shfl_sync(0xffffffffu, p.x, k + 2);
            int   c3 = __shfl_sync(0xffffffffu, p.x, k + 3);
            float v0 = __int_as_float(__shfl_sync(0xffffffffu, p.y, k));
            float v1 = __int_as_float(__shfl_sync(0xffffffffu, p.y, k + 1));
            float v2 = __int_as_float(__shfl_sync(0xffffffffu, p.y, k + 2));
            float v3 = __int_as_float(__shfl_sync(0xffffffffu, p.y, k + 3));
            uint2 d0 = __ldg(reinterpret_cast<const uint2*>(dense + (size_t)c0 * OUT_CH) + lane);
            uint2 d1 = __ldg(reinterpret_cast<const uint2*>(dense + (size_t)c1 * OUT_CH) + lane);
            uint2 d2 = __ldg(reinterpret_cast<const uint2*>(dense + (size_t)c2 * OUT_CH) + lane);
            uint2 d3 = __ldg(reinterpret_cast<const uint2*>(dense + (size_t)c3 * OUT_CH) + lane);
            fma_row(acc, v0, d0);
            fma_row(acc, v1, d1);
            fma_row(acc, v2, d2);
            fma_row(acc, v3, d3);
        }
        for (; k < n; k++) {
            int   c0 = __shfl_sync(0xffffffffu, p.x, k);
            float v0 = __int_as_float(__shfl_sync(0xffffffffu, p.y, k));
            uint2 d0 = __ldg(reinterpret_cast<const uint2*>(dense + (size_t)c0 * OUT_CH) + lane);
            fma_row(acc, v0, d0);
        }
    }

    if (RELU_BIAS) {
        float4 b = __ldg(reinterpret_cast<const float4*>(bias) + lane);
        acc.x = fmaxf(acc.x + b.x, 0.f);
        acc.y = fmaxf(acc.y + b.y, 0.f);
        acc.z = fmaxf(acc.z + b.z, 0.f);
        acc.w = fmaxf(acc.w + b.w, 0.f);
    }

    if (OUT_HALF) {
        __half2 lo = __floats2half2_rn(acc.x, acc.y);
        __half2 hi = __floats2half2_rn(acc.z, acc.w);
        uint2 st;
        st.x = *reinterpret_cast<uint32_t*>(&lo);
        st.y = *reinterpret_cast<uint32_t*>(&hi);
        reinterpret_cast<uint2*>(outv)[(size_t)w * 32 + lane] = st;
    } else {
        reinterpret_cast<float4*>(outv)[(size_t)w * 32 + lane] = acc;
    }
}

// ---------------- launch ----------------------------------------------------
extern "C" void kernel_launch(void* const* d_in, const int* in_sizes, int n_in,
                              void* d_out, int out_size)
{
    const int*   feat_rows = (const int*)  d_in[0];
    const int*   feat_cols = (const int*)  d_in[1];
    const float* feat_vals = (const float*)d_in[2];
    const int*   adj_rows  = (const int*)  d_in[3];
    const int*   adj_cols  = (const int*)  d_in[4];
    const float* adj_vals  = (const float*)d_in[5];
    const float* weight    = (const float*)d_in[6];
    const float* bias      = (const float*)d_in[7];
    float*       out       = (float*)      d_out;

    __half *h0, *h1, *wh;
    int *rp_f, *rp_a, *cnt, *incl, *bsum, *cursor;
    int2 *pk_f, *pk_a;
    cudaGetSymbolAddress((void**)&h0,     g_h0);
    cudaGetSymbolAddress((void**)&h1,     g_h1);
    cudaGetSymbolAddress((void**)&wh,     g_Wh);
    cudaGetSymbolAddress((void**)&rp_f,   g_rowptr_feat);
    cudaGetSymbolAddress((void**)&rp_a,   g_rowptr_adj);
    cudaGetSymbolAddress((void**)&cnt,    g_cnt);
    cudaGetSymbolAddress((void**)&incl,   g_incl);
    cudaGetSymbolAddress((void**)&bsum,   g_bsum);
    cudaGetSymbolAddress((void**)&cursor, g_cursor);
    cudaGetSymbolAddress((void**)&pk_f,   g_feat_pack);
    cudaGetSymbolAddress((void**)&pk_a,   g_adj_pack);

    // W -> fp16
    convert_w_kernel<<<(IN_CH * OUT_CH + 255) / 256, 256>>>(weight, wh, IN_CH * OUT_CH);

    // Fused CSR build for both matrices (6 launches total).
    cudaMemsetAsync(cnt, 0, 2 * N_NODES * sizeof(int));
    hist2_kernel<<<(NNZ_TOT + 255) / 256, 256>>>(feat_rows, adj_rows, cnt);
    scan_block2_kernel<<<2 * SCAN_NBLK, SCAN_BLOCK>>>(cnt, incl, bsum);
    scan_bsum2_kernel<<<1, 64>>>(bsum);
    finalize2_kernel<<<(2 * N_NODES + 255) / 256, 256>>>(cnt, incl, bsum,
                                                         rp_f, rp_a, cursor);
    scatter2_kernel<<<(NNZ_TOT + 255) / 256, 256>>>(feat_rows, feat_cols, feat_vals,
                                                    adj_rows, adj_cols, adj_vals,
                                                    cursor, pk_f, pk_a);

    const int gather_blocks = (N_NODES * 32 + 255) / 256;   // one warp per row

    // Layer 1: h0 = relu(feat @ W + bias), stored fp16
    spmm_gather_kernel<true,  true ><<<gather_blocks, 256>>>(rp_f, pk_f, wh, bias,
                                                             h0, N_NODES);
    // Iterations 2..3: fp16 -> fp16
    spmm_gather_kernel<false, true ><<<gather_blocks, 256>>>(rp_a, pk_a, h0, nullptr,
                                                             h1, N_NODES);
    spmm_gather_kernel<false, true ><<<gather_blocks, 256>>>(rp_a, pk_a, h1, nullptr,
                                                             h0, N_NODES);
    // Iteration 4: fp16 -> fp32 final output (no quantization on last write)
    spmm_gather_kernel<false, false><<<gather_blocks, 256>>>(rp_a, pk_a, h0, nullptr,
                                                             out, N_NODES);
}